// round 12
// baseline (speedup 1.0000x reference)
#include <cuda_runtime.h>
#include <cuda_fp16.h>
#include <cstdint>
#include <math.h>

#define Nn 8192
#define NH 64
#define NC 8
#define MAXE (Nn * 32)

// ------------------------- device scratch (static, no allocs) ----------------
__device__ float  g_S1[Nn * NH];
__device__ __half g_S1h[Nn * NH];
__device__ __half g_S2h[Nn * NH];
__device__ float  g_S3[Nn * NC];
__device__ __half g_W1T_hi[NH * Nn];
__device__ int   g_cnt[Nn];
__device__ int   g_off[Nn];
__device__ int   g_rowptr[Nn + 1];
__device__ int   g_cols[MAXE];
__device__ float g_vals[MAXE];

// ------------------------- HMMA / async helpers ------------------------------
__device__ __forceinline__ void mma16816(float c[4], const uint32_t a[4],
                                         uint32_t b0, uint32_t b1) {
    asm volatile(
        "mma.sync.aligned.m16n8k16.row.col.f32.f16.f16.f32 "
        "{%0,%1,%2,%3}, {%4,%5,%6,%7}, {%8,%9}, {%0,%1,%2,%3};"
        : "+f"(c[0]), "+f"(c[1]), "+f"(c[2]), "+f"(c[3])
        : "r"(a[0]), "r"(a[1]), "r"(a[2]), "r"(a[3]), "r"(b0), "r"(b1));
}

__device__ __forceinline__ void ldsm_x4(uint32_t& r0, uint32_t& r1,
                                        uint32_t& r2, uint32_t& r3, uint32_t addr) {
    asm volatile("ldmatrix.sync.aligned.m8n8.x4.shared.b16 {%0,%1,%2,%3}, [%4];"
                 : "=r"(r0), "=r"(r1), "=r"(r2), "=r"(r3) : "r"(addr));
}

__device__ __forceinline__ void cp_async16(uint32_t dst, const void* src) {
    asm volatile("cp.async.cg.shared.global [%0], [%1], 16;" :: "r"(dst), "l"(src));
}
__device__ __forceinline__ void cp_commit() {
    asm volatile("cp.async.commit_group;");
}
template <int N>
__device__ __forceinline__ void cp_wait() {
    asm volatile("cp.async.wait_group %0;" :: "n"(N));
}

__device__ __forceinline__ uint32_t pack_h2(float x, float y) {
    __half2 h = __floats2half2_rn(x, y);
    return *reinterpret_cast<uint32_t*>(&h);
}

// ------------------------- setup: zero S1/cnt/off, out init ------------------
__global__ void setup_kernel(const float* __restrict__ blin, float* __restrict__ out) {
    int i = blockIdx.x * blockDim.x + threadIdx.x;
    reinterpret_cast<float4*>(g_S1)[i] = make_float4(0.f, 0.f, 0.f, 0.f);
    if (i < Nn) { g_cnt[i] = 0; g_off[i] = 0; }
    if (i < NC) out[i] = blin[0];
}

// ------------------------- hist (vectorized, 8/thread) -----------------------
__global__ void hist_kernel(const int* __restrict__ row, int E) {
    int i = (blockIdx.x * blockDim.x + threadIdx.x) * 8;
    if (i + 7 < E) {
        int4 r0 = *reinterpret_cast<const int4*>(row + i);
        int4 r1 = *reinterpret_cast<const int4*>(row + i + 4);
        atomicAdd(&g_cnt[r0.x], 1); atomicAdd(&g_cnt[r0.y], 1);
        atomicAdd(&g_cnt[r0.z], 1); atomicAdd(&g_cnt[r0.w], 1);
        atomicAdd(&g_cnt[r1.x], 1); atomicAdd(&g_cnt[r1.y], 1);
        atomicAdd(&g_cnt[r1.z], 1); atomicAdd(&g_cnt[r1.w], 1);
    } else {
        for (int j = i; j < E; j++) atomicAdd(&g_cnt[row[j]], 1);
    }
}

// ------------------------- W1 transpose (coalesced, smem tile) ---------------
__global__ void transpose_w1(const float* __restrict__ W1) {
    __shared__ float t[32][65];
    int k0 = blockIdx.x * 32;
    int tid = threadIdx.x;
    #pragma unroll
    for (int i = 0; i < 8; i++) {
        int j = tid + i * 256;
        int r = j >> 6, c = j & 63;
        t[r][c] = W1[(size_t)(k0 + r) * NH + c];
    }
    __syncthreads();
    #pragma unroll
    for (int i = 0; i < 8; i++) {
        int j = tid + i * 256;
        int c = j >> 5, r = j & 31;
        g_W1T_hi[(size_t)c * Nn + k0 + r] = __float2half_rn(t[r][c]);
    }
}

// ------------------------- shfl exclusive scan (1024 threads) ----------------
__global__ void scan_kernel() {
    __shared__ int wsum[32];
    int t = threadIdx.x, lane = t & 31, w = t >> 5;
    int base = t * 8;
    int s = 0;
    #pragma unroll
    for (int i = 0; i < 8; i++) s += g_cnt[base + i];
    int incl = s;
    #pragma unroll
    for (int o = 1; o < 32; o <<= 1) {
        int v = __shfl_up_sync(0xFFFFFFFFu, incl, o);
        if (lane >= o) incl += v;
    }
    if (lane == 31) wsum[w] = incl;
    __syncthreads();
    if (w == 0) {
        int v = wsum[lane];
        int iw = v;
        #pragma unroll
        for (int o = 1; o < 32; o <<= 1) {
            int u = __shfl_up_sync(0xFFFFFFFFu, iw, o);
            if (lane >= o) iw += u;
        }
        wsum[lane] = iw - v;
    }
    __syncthreads();
    int acc = incl - s + wsum[w];
    #pragma unroll
    for (int i = 0; i < 8; i++) { g_rowptr[base + i] = acc; acc += g_cnt[base + i]; }
    if (t == 1023) g_rowptr[Nn] = acc;
}

__global__ void scatter_kernel(const int* __restrict__ row, const int* __restrict__ col,
                               const float* __restrict__ val, int E) {
    int e = blockIdx.x * blockDim.x + threadIdx.x;
    if (e < E) {
        int r = row[e];
        int p = g_rowptr[r] + atomicAdd(&g_off[r], 1);
        g_cols[p] = col[e];
        g_vals[p] = val[e];
    }
}

// ------------------------- GEMM1: direct-LDG A, smem B only ------------------
// S1 += x @ W1. Grid 256 = 64 m-tiles(128 rows) x 4 K-quarters; 8 warps/CTA,
// warp owns 16 m-rows x full n=64. A fragments LDG.64 direct to registers
// (double-buffered, MLP 16/warp, sector-perfect); B (8KB/chunk) in 4-stage
// cp.async ring read via ldmatrix.x4. Epilogue: atomicAdd into zeroed g_S1.
#define BSTAGE 9216
__global__ void __launch_bounds__(256, 2)
gemm1_hmma(const float* __restrict__ Aext) {
    extern __shared__ char smem[];
    const uint32_t sb = (uint32_t)__cvta_generic_to_shared(smem);
    const int tid = threadIdx.x, lane = tid & 31, w = tid >> 5;
    const int g = lane >> 2, tg = lane & 3;
    const int m0 = (blockIdx.x >> 2) * 128;
    const int kq = blockIdx.x & 3;
    const int row = m0 + w * 16 + g;

    float acc[8][4];
    #pragma unroll
    for (int nt = 0; nt < 8; nt++)
        #pragma unroll
        for (int q = 0; q < 4; q++) acc[nt][q] = 0.f;

    // A per-thread base: x[row][kq*2048 + 2*tg]
    const float* pa = Aext + (size_t)row * Nn + kq * 2048 + 2 * tg;

    // B cp.async: 512 16B units over 256 threads (2 each)
    const __half* bbase = g_W1T_hi + (size_t)(tid >> 3) * Nn + kq * 2048 + (tid & 7) * 8;
    const uint32_t bdst0 = (tid >> 3) * 144 + (tid & 7) * 16;
    auto issueB = [&](int kc) {
        uint32_t dbase = sb + (kc & 3) * BSTAGE;
        const __half* bs = bbase + kc * 64;
        cp_async16(dbase + bdst0, bs);
        cp_async16(dbase + bdst0 + 32 * 144, bs + 32 * Nn);
    };
    // ldmatrix lane address (4 x4-loads per ks at +0,+2304,+4608,+6912)
    const uint32_t lmb =
        (uint32_t)((((lane >> 4) * 8) + (lane & 7)) * 144 + ((lane >> 3) & 1) * 16);

    float2 av0[16], av1[16];
    auto loadA = [&](int kc, float2* buf) {
        const float* p = pa + kc * 64;
        #pragma unroll
        for (int ks = 0; ks < 4; ks++)
            #pragma unroll
            for (int i = 0; i < 4; i++)
                buf[ks * 4 + i] = *reinterpret_cast<const float2*>(
                    p + ks * 16 + (i >> 1) * 8 + (size_t)(i & 1) * 8 * Nn);
    };

    auto step = [&](int kc, const float2* cur, float2* nxt) {
        if (kc + 1 < 32) loadA(kc + 1, nxt);
        cp_wait<2>();
        __syncthreads();
        if (kc + 3 < 32) issueB(kc + 3);
        cp_commit();
        const uint32_t bb = sb + (kc & 3) * BSTAGE + lmb;
        #pragma unroll
        for (int ks = 0; ks < 4; ks++) {
            uint32_t ah[4];
            #pragma unroll
            for (int i = 0; i < 4; i++)
                ah[i] = pack_h2(cur[ks * 4 + i].x, cur[ks * 4 + i].y);
            uint32_t b[16];
            ldsm_x4(b[0],  b[1],  b[2],  b[3],  bb + ks * 32);
            ldsm_x4(b[4],  b[5],  b[6],  b[7],  bb + ks * 32 + 2304);
            ldsm_x4(b[8],  b[9],  b[10], b[11], bb + ks * 32 + 4608);
            ldsm_x4(b[12], b[13], b[14], b[15], bb + ks * 32 + 6912);
            #pragma unroll
            for (int nt = 0; nt < 8; nt++)
                mma16816(acc[nt], ah, b[2 * nt], b[2 * nt + 1]);
        }
    };

    issueB(0); cp_commit();
    issueB(1); cp_commit();
    issueB(2); cp_commit();
    loadA(0, av0);
    #pragma unroll 1
    for (int kp = 0; kp < 16; kp++) {
        step(2 * kp,     av0, av1);
        step(2 * kp + 1, av1, av0);
    }

    #pragma unroll
    for (int nt = 0; nt < 8; nt++) {
        int col = nt * 8 + 2 * tg;
        atomicAdd(&g_S1[(size_t)row * 64 + col],           acc[nt][0]);
        atomicAdd(&g_S1[(size_t)row * 64 + col + 1],       acc[nt][1]);
        atomicAdd(&g_S1[(size_t)(row + 8) * 64 + col],     acc[nt][2]);
        atomicAdd(&g_S1[(size_t)(row + 8) * 64 + col + 1], acc[nt][3]);
    }
}

// ------------------------- S1 fp32 -> fp16 convert ---------------------------
__global__ void convert_s1h() {
    int i = blockIdx.x * blockDim.x + threadIdx.x;
    const float4* src = reinterpret_cast<const float4*>(g_S1);
    float4 a = src[2 * i], b = src[2 * i + 1];
    uint4 u;
    u.x = pack_h2(a.x, a.y);
    u.y = pack_h2(a.z, a.w);
    u.z = pack_h2(b.x, b.y);
    u.w = pack_h2(b.z, b.w);
    reinterpret_cast<uint4*>(g_S1h)[i] = u;
}

// ------------------------- SpMM1 (fp16 gathers) + bias + relu + GEMM2 --------
__global__ void spmm1_g2(const float* __restrict__ b1, const float* __restrict__ W2) {
    __shared__ float w2s[NH * NH];
    int tid = threadIdx.x;
    #pragma unroll
    for (int i = 0; i < 16; i++) w2s[tid + i * 256] = W2[tid + i * 256];
    __syncthreads();
    int gt = blockIdx.x * blockDim.x + tid;
    int row = gt >> 5, lane = gt & 31;
    int s = g_rowptr[row], e = g_rowptr[row + 1];
    const __half2* S = reinterpret_cast<const __half2*>(g_S1h);
    float a0 = 0.f, a1 = 0.f;
    int i = s;
    for (; i + 4 <= e; i += 4) {
        int   c0 = g_cols[i],     c1 = g_cols[i + 1];
        int   c2 = g_cols[i + 2], c3 = g_cols[i + 3];
        float v0 = g_vals[i],     v1 = g_vals[i + 1];
        float v2 = g_vals[i + 2], v3 = g_vals[i + 3];
        float2 f0 = __half22float2(S[(size_t)c0 * 32 + lane]);
        float2 f1 = __half22float2(S[(size_t)c1 * 32 + lane]);
        float2 f2 = __half22float2(S[(size_t)c2 * 32 + lane]);
        float2 f3 = __half22float2(S[(size_t)c3 * 32 + lane]);
        a0 += v0 * f0.x; a1 += v0 * f0.y;
        a0 += v1 * f1.x; a1 += v1 * f1.y;
        a0 += v2 * f2.x; a1 += v2 * f2.y;
        a0 += v3 * f3.x; a1 += v3 * f3.y;
    }
    for (; i < e; i++) {
        float2 f = __half22float2(S[(size_t)g_cols[i] * 32 + lane]);
        float v = g_vals[i];
        a0 += v * f.x; a1 += v * f.y;
    }
    float2 bb = *reinterpret_cast<const float2*>(b1 + 2 * lane);
    float r0 = fmaxf(a0 + bb.x, 0.f);
    float r1 = fmaxf(a1 + bb.y, 0.f);
    float acc0 = 0.f, acc1 = 0.f;
    #pragma unroll
    for (int j = 0; j < 32; j++) {
        float hk0 = __shfl_sync(0xFFFFFFFFu, r0, j);
        float hk1 = __shfl_sync(0xFFFFFFFFu, r1, j);
        float2 wa = *reinterpret_cast<const float2*>(w2s + (2 * j) * 64 + 2 * lane);
        float2 wb = *reinterpret_cast<const float2*>(w2s + (2 * j + 1) * 64 + 2 * lane);
        acc0 += hk0 * wa.x + hk1 * wb.x;
        acc1 += hk0 * wa.y + hk1 * wb.y;
    }
    reinterpret_cast<__half2*>(g_S2h)[(size_t)row * 32 + lane] =
        __floats2half2_rn(acc0, acc1);
}

// ------------------------- SpMM2 (fp16 gathers) + bias + relu + gemm3 --------
__global__ void spmm2_g3(const float* __restrict__ b2, const float* __restrict__ W3) {
    __shared__ float w3t[NC * NH];
    int tid = threadIdx.x;
    #pragma unroll
    for (int ii = 0; ii < 2; ii++) {
        int i = tid + ii * 256;
        w3t[(i & 7) * 64 + (i >> 3)] = W3[i];
    }
    __syncthreads();
    int gt = blockIdx.x * blockDim.x + tid;
    int row = gt >> 5, lane = gt & 31;
    int s = g_rowptr[row], e = g_rowptr[row + 1];
    const __half2* S = reinterpret_cast<const __half2*>(g_S2h);
    float a0 = 0.f, a1 = 0.f;
    int i = s;
    for (; i + 4 <= e; i += 4) {
        int   c0 = g_cols[i],     c1 = g_cols[i + 1];
        int   c2 = g_cols[i + 2], c3 = g_cols[i + 3];
        float v0 = g_vals[i],     v1 = g_vals[i + 1];
        float v2 = g_vals[i + 2], v3 = g_vals[i + 3];
        float2 f0 = __half22float2(S[(size_t)c0 * 32 + lane]);
        float2 f1 = __half22float2(S[(size_t)c1 * 32 + lane]);
        float2 f2 = __half22float2(S[(size_t)c2 * 32 + lane]);
        float2 f3 = __half22float2(S[(size_t)c3 * 32 + lane]);
        a0 += v0 * f0.x; a1 += v0 * f0.y;
        a0 += v1 * f1.x; a1 += v1 * f1.y;
        a0 += v2 * f2.x; a1 += v2 * f2.y;
        a0 += v3 * f3.x; a1 += v3 * f3.y;
    }
    for (; i < e; i++) {
        float2 f = __half22float2(S[(size_t)g_cols[i] * 32 + lane]);
        float v = g_vals[i];
        a0 += v * f.x; a1 += v * f.y;
    }
    float2 bb = *reinterpret_cast<const float2*>(b2 + 2 * lane);
    float r0 = fmaxf(a0 + bb.x, 0.f);
    float r1 = fmaxf(a1 + bb.y, 0.f);
    float p[NC];
    #pragma unroll
    for (int f = 0; f < NC; f++) {
        float2 wv = *reinterpret_cast<const float2*>(w3t + f * 64 + 2 * lane);
        p[f] = r0 * wv.x + r1 * wv.y;
    }
    #pragma unroll
    for (int o = 16; o > 0; o >>= 1)
        #pragma unroll
        for (int f = 0; f < NC; f++) p[f] += __shfl_xor_sync(0xFFFFFFFFu, p[f], o);
    if (lane == 0) {
        float* o8 = g_S3 + (size_t)row * NC;
        *reinterpret_cast<float4*>(o8)     = make_float4(p[0], p[1], p[2], p[3]);
        *reinterpret_cast<float4*>(o8 + 4) = make_float4(p[4], p[5], p[6], p[7]);
    }
}

// ------------------------- final: warp-per-row spmm8 + softmax + head --------
__global__ void final_fused(const float* __restrict__ b3, const float* __restrict__ Wlin,
                            float* __restrict__ out) {
    __shared__ float red[8][NC];
    int t = threadIdx.x, lane = t & 31, wp = t >> 5;
    int row = blockIdx.x * 8 + wp;
    float acc[NC];
    #pragma unroll
    for (int f = 0; f < NC; f++) acc[f] = 0.f;
    int s = g_rowptr[row], e = g_rowptr[row + 1];
    for (int i = s + lane; i < e; i += 32) {
        int c = g_cols[i];
        float v = g_vals[i];
        const float4* p = reinterpret_cast<const float4*>(g_S3 + (size_t)c * NC);
        float4 q0 = p[0], q1 = p[1];
        acc[0] += v * q0.x; acc[1] += v * q0.y; acc[2] += v * q0.z; acc[3] += v * q0.w;
        acc[4] += v * q1.x; acc[5] += v * q1.y; acc[6] += v * q1.z; acc[7] += v * q1.w;
    }
    #pragma unroll
    for (int o = 16; o > 0; o >>= 1)
        #pragma unroll
        for (int f = 0; f < NC; f++) acc[f] += __shfl_xor_sync(0xFFFFFFFFu, acc[f], o);
    if (lane == 0) {
        float h[NC];
        #pragma unroll
        for (int f = 0; f < NC; f++) h[f] = acc[f] + b3[f];
        float m = h[0];
        #pragma unroll
        for (int f = 1; f < NC; f++) m = fmaxf(m, h[f]);
        float ssum = 0.f;
        #pragma unroll
        for (int f = 0; f < NC; f++) ssum += expf(h[f] - m);
        float lse = m + logf(ssum);
        float wv = Wlin[row];
        #pragma unroll
        for (int f = 0; f < NC; f++) red[wp][f] = (h[f] - lse) * wv;
    }
    __syncthreads();
    if (t < NC) {
        float ssum = 0.f;
        #pragma unroll
        for (int j = 0; j < 8; j++) ssum += red[j][t];
        atomicAdd(&out[t], ssum);
    }
}

// ------------------------- launch -------------------------------------------
extern "C" void kernel_launch(void* const* d_in, const int* in_sizes, int n_in,
                              void* d_out, int out_size) {
    const float* x    = (const float*)d_in[0];
    const int*   arow = (const int*)d_in[1];
    const int*   acol = (const int*)d_in[2];
    const float* aval = (const float*)d_in[3];
    const float* W1   = (const float*)d_in[4];
    const float* b1   = (const float*)d_in[5];
    const float* W2   = (const float*)d_in[6];
    const float* b2   = (const float*)d_in[7];
    const float* W3   = (const float*)d_in[8];
    const float* b3   = (const float*)d_in[9];
    const float* Wlin = (const float*)d_in[10];
    const float* blin = (const float*)d_in[11];
    const int E = in_sizes[1];
    float* out = (float*)d_out;

    static cudaStream_t s_side = nullptr;
    static cudaEvent_t ev_fork, ev_w1, ev_join;
    if (!s_side) {
        cudaStreamCreateWithFlags(&s_side, cudaStreamNonBlocking);
        cudaEventCreateWithFlags(&ev_fork, cudaEventDisableTiming);
        cudaEventCreateWithFlags(&ev_w1, cudaEventDisableTiming);
        cudaEventCreateWithFlags(&ev_join, cudaEventDisableTiming);
        cudaFuncSetAttribute(gemm1_hmma, cudaFuncAttributeMaxDynamicSharedMemorySize,
                             4 * BSTAGE);
    }

    // fork side stream at capture start
    cudaEventRecord(ev_fork, 0);
    cudaStreamWaitEvent(s_side, ev_fork, 0);

    // side stream: W1 transpose, then CSR build
    transpose_w1<<<Nn / 32, 256, 0, s_side>>>(W1);
    cudaEventRecord(ev_w1, s_side);
    hist_kernel<<<(E / 8 + 255) / 256, 256, 0, s_side>>>(arow, E);
    scan_kernel<<<1, 1024, 0, s_side>>>();
    scatter_kernel<<<(E + 255) / 256, 256, 0, s_side>>>(arow, acol, aval, E);
    cudaEventRecord(ev_join, s_side);

    // main stream: setup, then GEMM1 (after W1T ready) + convert
    setup_kernel<<<512, 256>>>(blin, out);
    cudaStreamWaitEvent(0, ev_w1, 0);
    gemm1_hmma<<<256, 256, 4 * BSTAGE>>>(x);
    convert_s1h<<<256, 256>>>();

    // join CSR, then spmm chain
    cudaStreamWaitEvent(0, ev_join, 0);
    spmm1_g2<<<(Nn * 32) / 256, 256>>>(b1, W2);
    spmm2_g3<<<(Nn * 32) / 256, 256>>>(b2, W3);
    final_fused<<<Nn / 8, 256>>>(b3, Wlin, out);
}

// round 13
// speedup vs baseline: 1.0800x; 1.0800x over previous
#include <cuda_runtime.h>
#include <cuda_fp16.h>
#include <cstdint>
#include <math.h>

#define Nn 8192
#define NH 64
#define NC 8
#define MAXE (Nn * 32)

// ------------------------- device scratch (static, no allocs) ----------------
__device__ float  g_S1[Nn * NH];
__device__ __half g_S1h[Nn * NH];
__device__ __half g_S2h[Nn * NH];
__device__ float  g_S3[Nn * NC];
__device__ __half g_W1T_hi[NH * Nn];
__device__ int   g_cnt[Nn];
__device__ int   g_off[Nn];
__device__ int   g_rowptr[Nn + 1];
__device__ int   g_cols[MAXE];
__device__ float g_vals[MAXE];

#define SWZ(o)  ((o) ^ (((o) >> 3) & 0x70))

// ------------------------- HMMA / async helpers ------------------------------
__device__ __forceinline__ void mma16816(float c[4], const uint32_t a[4],
                                         uint32_t b0, uint32_t b1) {
    asm volatile(
        "mma.sync.aligned.m16n8k16.row.col.f32.f16.f16.f32 "
        "{%0,%1,%2,%3}, {%4,%5,%6,%7}, {%8,%9}, {%0,%1,%2,%3};"
        : "+f"(c[0]), "+f"(c[1]), "+f"(c[2]), "+f"(c[3])
        : "r"(a[0]), "r"(a[1]), "r"(a[2]), "r"(a[3]), "r"(b0), "r"(b1));
}

__device__ __forceinline__ void ldsm_x4(uint32_t& r0, uint32_t& r1,
                                        uint32_t& r2, uint32_t& r3, uint32_t addr) {
    asm volatile("ldmatrix.sync.aligned.m8n8.x4.shared.b16 {%0,%1,%2,%3}, [%4];"
                 : "=r"(r0), "=r"(r1), "=r"(r2), "=r"(r3) : "r"(addr));
}

__device__ __forceinline__ void cp_async16(uint32_t dst, const void* src) {
    asm volatile("cp.async.cg.shared.global [%0], [%1], 16;" :: "r"(dst), "l"(src));
}
__device__ __forceinline__ void cp_commit() {
    asm volatile("cp.async.commit_group;");
}
template <int N>
__device__ __forceinline__ void cp_wait() {
    asm volatile("cp.async.wait_group %0;" :: "n"(N));
}

__device__ __forceinline__ uint32_t pack_h2(float x, float y) {
    __half2 h = __floats2half2_rn(x, y);
    return *reinterpret_cast<uint32_t*>(&h);
}

// ------------------------- setup: zero S1/cnt/off, out init ------------------
__global__ void setup_kernel(const float* __restrict__ blin, float* __restrict__ out) {
    int i = blockIdx.x * blockDim.x + threadIdx.x;
    reinterpret_cast<float4*>(g_S1)[i] = make_float4(0.f, 0.f, 0.f, 0.f);
    if (i < Nn) { g_cnt[i] = 0; g_off[i] = 0; }
    if (i < NC) out[i] = blin[0];
}

// ------------------------- hist (vectorized, 8/thread) -----------------------
__global__ void hist_kernel(const int* __restrict__ row, int E) {
    int i = (blockIdx.x * blockDim.x + threadIdx.x) * 8;
    if (i + 7 < E) {
        int4 r0 = *reinterpret_cast<const int4*>(row + i);
        int4 r1 = *reinterpret_cast<const int4*>(row + i + 4);
        atomicAdd(&g_cnt[r0.x], 1); atomicAdd(&g_cnt[r0.y], 1);
        atomicAdd(&g_cnt[r0.z], 1); atomicAdd(&g_cnt[r0.w], 1);
        atomicAdd(&g_cnt[r1.x], 1); atomicAdd(&g_cnt[r1.y], 1);
        atomicAdd(&g_cnt[r1.z], 1); atomicAdd(&g_cnt[r1.w], 1);
    } else {
        for (int j = i; j < E; j++) atomicAdd(&g_cnt[row[j]], 1);
    }
}

// ------------------------- W1 transpose (coalesced, smem tile) ---------------
__global__ void transpose_w1(const float* __restrict__ W1) {
    __shared__ float t[32][65];
    int k0 = blockIdx.x * 32;
    int tid = threadIdx.x;
    #pragma unroll
    for (int i = 0; i < 8; i++) {
        int j = tid + i * 256;
        int r = j >> 6, c = j & 63;
        t[r][c] = W1[(size_t)(k0 + r) * NH + c];
    }
    __syncthreads();
    #pragma unroll
    for (int i = 0; i < 8; i++) {
        int j = tid + i * 256;
        int c = j >> 5, r = j & 31;
        g_W1T_hi[(size_t)c * Nn + k0 + r] = __float2half_rn(t[r][c]);
    }
}

// ------------------------- shfl exclusive scan (1024 threads) ----------------
__global__ void scan_kernel() {
    __shared__ int wsum[32];
    int t = threadIdx.x, lane = t & 31, w = t >> 5;
    int base = t * 8;
    int s = 0;
    #pragma unroll
    for (int i = 0; i < 8; i++) s += g_cnt[base + i];
    int incl = s;
    #pragma unroll
    for (int o = 1; o < 32; o <<= 1) {
        int v = __shfl_up_sync(0xFFFFFFFFu, incl, o);
        if (lane >= o) incl += v;
    }
    if (lane == 31) wsum[w] = incl;
    __syncthreads();
    if (w == 0) {
        int v = wsum[lane];
        int iw = v;
        #pragma unroll
        for (int o = 1; o < 32; o <<= 1) {
            int u = __shfl_up_sync(0xFFFFFFFFu, iw, o);
            if (lane >= o) iw += u;
        }
        wsum[lane] = iw - v;
    }
    __syncthreads();
    int acc = incl - s + wsum[w];
    #pragma unroll
    for (int i = 0; i < 8; i++) { g_rowptr[base + i] = acc; acc += g_cnt[base + i]; }
    if (t == 1023) g_rowptr[Nn] = acc;
}

__global__ void scatter_kernel(const int* __restrict__ row, const int* __restrict__ col,
                               const float* __restrict__ val, int E) {
    int e = blockIdx.x * blockDim.x + threadIdx.x;
    if (e < E) {
        int r = row[e];
        int p = g_rowptr[r] + atomicAdd(&g_off[r], 1);
        g_cols[p] = col[e];
        g_vals[p] = val[e];
    }
}

// ------------------------- HMMA GEMM1 (R11 proven config) --------------------
// S1 += x @ W1. K split x4 (grid 512, 2 CTAs/SM). 4 stages x 25.6KB,
// prefetch 3, wait_group 2, commit every iteration. A via cp.async fp32
// swizzled smem -> cvt at fragment read; B via ldmatrix.x4.
#define SLAB0 25600
__global__ void __launch_bounds__(256, 2)
gemm1_hmma(const float* __restrict__ Aext) {
    extern __shared__ char smem[];
    const uint32_t sb = (uint32_t)__cvta_generic_to_shared(smem);
    const int tid = threadIdx.x, lane = tid & 31, w = tid >> 5;
    const int wm = (w & 3) * 16, wn = (w >> 2) * 32;
    const int g = lane >> 2, tg = lane & 3;

    float acc[4][4];
    #pragma unroll
    for (int nt = 0; nt < 4; nt++)
        #pragma unroll
        for (int q = 0; q < 4; q++) acc[nt][q] = 0.f;

    uint32_t aoff[16];
    #pragma unroll
    for (int ks = 0; ks < 4; ks++)
        #pragma unroll
        for (int i = 0; i < 4; i++) {
            uint32_t o = (uint32_t)((wm + g + (i & 1) * 8) * 256 +
                                    ks * 64 + tg * 8 + (i >> 1) * 32);
            aoff[ks * 4 + i] = SWZ(o);
        }

    const int m0 = (blockIdx.x >> 2) * 64;
    const int kq = blockIdx.x & 3;
    const float* abase = Aext + (size_t)(m0 + (tid >> 4)) * Nn + kq * 2048 + (tid & 15) * 4;
    const uint32_t adst0 = SWZ((uint32_t)((tid >> 4) * 256 + (tid & 15) * 16));
    const __half* bbase = g_W1T_hi + (size_t)(tid >> 3) * Nn + kq * 2048 + (tid & 7) * 8;
    const uint32_t bdst0 = 16384u + (tid >> 3) * 144 + (tid & 7) * 16;
    const uint32_t lmb = 16384u +
        (uint32_t)((wn + ((lane >> 4) * 8) + (lane & 7)) * 144 + ((lane >> 3) & 1) * 16);

    auto issue = [&](int kc) {
        uint32_t dbase = sb + (kc & 3) * SLAB0;
        const float* as = abase + kc * 64;
        #pragma unroll
        for (int ii = 0; ii < 4; ii++)
            cp_async16(dbase + adst0 + ii * 4096, as + ii * 16 * Nn);
        const __half* bs = bbase + kc * 64;
        #pragma unroll
        for (int ii = 0; ii < 2; ii++)
            cp_async16(dbase + bdst0 + ii * 32 * 144, bs + ii * 32 * Nn);
    };

    issue(0); cp_commit();
    issue(1); cp_commit();
    issue(2); cp_commit();
    #pragma unroll 1
    for (int kc = 0; kc < 32; kc++) {
        cp_wait<2>();
        __syncthreads();
        if (kc + 3 < 32) issue(kc + 3);
        cp_commit();
        const char* base = smem + (kc & 3) * SLAB0;
        const uint32_t bb = sb + (kc & 3) * SLAB0 + lmb;
        #pragma unroll
        for (int ks = 0; ks < 4; ks++) {
            uint32_t ah[4];
            #pragma unroll
            for (int i = 0; i < 4; i++) {
                float2 v = *reinterpret_cast<const float2*>(base + aoff[ks * 4 + i]);
                ah[i] = pack_h2(v.x, v.y);
            }
            uint32_t b00, b01, b10, b11, b20, b21, b30, b31;
            ldsm_x4(b00, b01, b10, b11, bb + ks * 32);
            ldsm_x4(b20, b21, b30, b31, bb + ks * 32 + 2304);
            mma16816(acc[0], ah, b00, b01);
            mma16816(acc[1], ah, b10, b11);
            mma16816(acc[2], ah, b20, b21);
            mma16816(acc[3], ah, b30, b31);
        }
    }
    #pragma unroll
    for (int nt = 0; nt < 4; nt++) {
        int row = m0 + wm + g;
        int col = wn + nt * 8 + 2 * tg;
        atomicAdd(&g_S1[(size_t)row * 64 + col],           acc[nt][0]);
        atomicAdd(&g_S1[(size_t)row * 64 + col + 1],       acc[nt][1]);
        atomicAdd(&g_S1[(size_t)(row + 8) * 64 + col],     acc[nt][2]);
        atomicAdd(&g_S1[(size_t)(row + 8) * 64 + col + 1], acc[nt][3]);
    }
}

// ------------------------- S1 fp32 -> fp16 convert ---------------------------
__global__ void convert_s1h() {
    int i = blockIdx.x * blockDim.x + threadIdx.x;
    const float4* src = reinterpret_cast<const float4*>(g_S1);
    float4 a = src[2 * i], b = src[2 * i + 1];
    uint4 u;
    u.x = pack_h2(a.x, a.y);
    u.y = pack_h2(a.z, a.w);
    u.z = pack_h2(b.x, b.y);
    u.w = pack_h2(b.z, b.w);
    reinterpret_cast<uint4*>(g_S1h)[i] = u;
}

// ------------------------- SpMM1 (fp16 gathers) + bias + relu + GEMM2 --------
__global__ void spmm1_g2(const float* __restrict__ b1, const float* __restrict__ W2) {
    __shared__ float w2s[NH * NH];
    int tid = threadIdx.x;
    #pragma unroll
    for (int i = 0; i < 16; i++) w2s[tid + i * 256] = W2[tid + i * 256];
    __syncthreads();
    int gt = blockIdx.x * blockDim.x + tid;
    int row = gt >> 5, lane = gt & 31;
    int s = g_rowptr[row], e = g_rowptr[row + 1];
    const __half2* S = reinterpret_cast<const __half2*>(g_S1h);
    float a0 = 0.f, a1 = 0.f;
    int i = s;
    for (; i + 4 <= e; i += 4) {
        int   c0 = g_cols[i],     c1 = g_cols[i + 1];
        int   c2 = g_cols[i + 2], c3 = g_cols[i + 3];
        float v0 = g_vals[i],     v1 = g_vals[i + 1];
        float v2 = g_vals[i + 2], v3 = g_vals[i + 3];
        float2 f0 = __half22float2(S[(size_t)c0 * 32 + lane]);
        float2 f1 = __half22float2(S[(size_t)c1 * 32 + lane]);
        float2 f2 = __half22float2(S[(size_t)c2 * 32 + lane]);
        float2 f3 = __half22float2(S[(size_t)c3 * 32 + lane]);
        a0 += v0 * f0.x; a1 += v0 * f0.y;
        a0 += v1 * f1.x; a1 += v1 * f1.y;
        a0 += v2 * f2.x; a1 += v2 * f2.y;
        a0 += v3 * f3.x; a1 += v3 * f3.y;
    }
    for (; i < e; i++) {
        float2 f = __half22float2(S[(size_t)g_cols[i] * 32 + lane]);
        float v = g_vals[i];
        a0 += v * f.x; a1 += v * f.y;
    }
    float2 bb = *reinterpret_cast<const float2*>(b1 + 2 * lane);
    float r0 = fmaxf(a0 + bb.x, 0.f);
    float r1 = fmaxf(a1 + bb.y, 0.f);
    float acc0 = 0.f, acc1 = 0.f;
    #pragma unroll
    for (int j = 0; j < 32; j++) {
        float hk0 = __shfl_sync(0xFFFFFFFFu, r0, j);
        float hk1 = __shfl_sync(0xFFFFFFFFu, r1, j);
        float2 wa = *reinterpret_cast<const float2*>(w2s + (2 * j) * 64 + 2 * lane);
        float2 wb = *reinterpret_cast<const float2*>(w2s + (2 * j + 1) * 64 + 2 * lane);
        acc0 += hk0 * wa.x + hk1 * wb.x;
        acc1 += hk0 * wa.y + hk1 * wb.y;
    }
    reinterpret_cast<__half2*>(g_S2h)[(size_t)row * 32 + lane] =
        __floats2half2_rn(acc0, acc1);
}

// ------------------------- SpMM2 (fp16 gathers) + bias + relu + gemm3 --------
__global__ void spmm2_g3(const float* __restrict__ b2, const float* __restrict__ W3) {
    __shared__ float w3t[NC * NH];
    int tid = threadIdx.x;
    #pragma unroll
    for (int ii = 0; ii < 2; ii++) {
        int i = tid + ii * 256;
        w3t[(i & 7) * 64 + (i >> 3)] = W3[i];
    }
    __syncthreads();
    int gt = blockIdx.x * blockDim.x + tid;
    int row = gt >> 5, lane = gt & 31;
    int s = g_rowptr[row], e = g_rowptr[row + 1];
    const __half2* S = reinterpret_cast<const __half2*>(g_S2h);
    float a0 = 0.f, a1 = 0.f;
    int i = s;
    for (; i + 4 <= e; i += 4) {
        int   c0 = g_cols[i],     c1 = g_cols[i + 1];
        int   c2 = g_cols[i + 2], c3 = g_cols[i + 3];
        float v0 = g_vals[i],     v1 = g_vals[i + 1];
        float v2 = g_vals[i + 2], v3 = g_vals[i + 3];
        float2 f0 = __half22float2(S[(size_t)c0 * 32 + lane]);
        float2 f1 = __half22float2(S[(size_t)c1 * 32 + lane]);
        float2 f2 = __half22float2(S[(size_t)c2 * 32 + lane]);
        float2 f3 = __half22float2(S[(size_t)c3 * 32 + lane]);
        a0 += v0 * f0.x; a1 += v0 * f0.y;
        a0 += v1 * f1.x; a1 += v1 * f1.y;
        a0 += v2 * f2.x; a1 += v2 * f2.y;
        a0 += v3 * f3.x; a1 += v3 * f3.y;
    }
    for (; i < e; i++) {
        float2 f = __half22float2(S[(size_t)g_cols[i] * 32 + lane]);
        float v = g_vals[i];
        a0 += v * f.x; a1 += v * f.y;
    }
    float2 bb = *reinterpret_cast<const float2*>(b2 + 2 * lane);
    float r0 = fmaxf(a0 + bb.x, 0.f);
    float r1 = fmaxf(a1 + bb.y, 0.f);
    float p[NC];
    #pragma unroll
    for (int f = 0; f < NC; f++) {
        float2 wv = *reinterpret_cast<const float2*>(w3t + f * 64 + 2 * lane);
        p[f] = r0 * wv.x + r1 * wv.y;
    }
    #pragma unroll
    for (int o = 16; o > 0; o >>= 1)
        #pragma unroll
        for (int f = 0; f < NC; f++) p[f] += __shfl_xor_sync(0xFFFFFFFFu, p[f], o);
    if (lane == 0) {
        float* o8 = g_S3 + (size_t)row * NC;
        *reinterpret_cast<float4*>(o8)     = make_float4(p[0], p[1], p[2], p[3]);
        *reinterpret_cast<float4*>(o8 + 4) = make_float4(p[4], p[5], p[6], p[7]);
    }
}

// ------------------------- final: warp-per-row spmm8 + softmax + head --------
__global__ void final_fused(const float* __restrict__ b3, const float* __restrict__ Wlin,
                            float* __restrict__ out) {
    __shared__ float red[8][NC];
    int t = threadIdx.x, lane = t & 31, wp = t >> 5;
    int row = blockIdx.x * 8 + wp;
    float acc[NC];
    #pragma unroll
    for (int f = 0; f < NC; f++) acc[f] = 0.f;
    int s = g_rowptr[row], e = g_rowptr[row + 1];
    for (int i = s + lane; i < e; i += 32) {
        int c = g_cols[i];
        float v = g_vals[i];
        const float4* p = reinterpret_cast<const float4*>(g_S3 + (size_t)c * NC);
        float4 q0 = p[0], q1 = p[1];
        acc[0] += v * q0.x; acc[1] += v * q0.y; acc[2] += v * q0.z; acc[3] += v * q0.w;
        acc[4] += v * q1.x; acc[5] += v * q1.y; acc[6] += v * q1.z; acc[7] += v * q1.w;
    }
    #pragma unroll
    for (int o = 16; o > 0; o >>= 1)
        #pragma unroll
        for (int f = 0; f < NC; f++) acc[f] += __shfl_xor_sync(0xFFFFFFFFu, acc[f], o);
    if (lane == 0) {
        float h[NC];
        #pragma unroll
        for (int f = 0; f < NC; f++) h[f] = acc[f] + b3[f];
        float m = h[0];
        #pragma unroll
        for (int f = 1; f < NC; f++) m = fmaxf(m, h[f]);
        float ssum = 0.f;
        #pragma unroll
        for (int f = 0; f < NC; f++) ssum += expf(h[f] - m);
        float lse = m + logf(ssum);
        float wv = Wlin[row];
        #pragma unroll
        for (int f = 0; f < NC; f++) red[wp][f] = (h[f] - lse) * wv;
    }
    __syncthreads();
    if (t < NC) {
        float ssum = 0.f;
        #pragma unroll
        for (int j = 0; j < 8; j++) ssum += red[j][t];
        atomicAdd(&out[t], ssum);
    }
}

// ------------------------- launch -------------------------------------------
extern "C" void kernel_launch(void* const* d_in, const int* in_sizes, int n_in,
                              void* d_out, int out_size) {
    const float* x    = (const float*)d_in[0];
    const int*   arow = (const int*)d_in[1];
    const int*   acol = (const int*)d_in[2];
    const float* aval = (const float*)d_in[3];
    const float* W1   = (const float*)d_in[4];
    const float* b1   = (const float*)d_in[5];
    const float* W2   = (const float*)d_in[6];
    const float* b2   = (const float*)d_in[7];
    const float* W3   = (const float*)d_in[8];
    const float* b3   = (const float*)d_in[9];
    const float* Wlin = (const float*)d_in[10];
    const float* blin = (const float*)d_in[11];
    const int E = in_sizes[1];
    float* out = (float*)d_out;

    static cudaStream_t s_side = nullptr;
    static cudaEvent_t ev_fork, ev_w1, ev_join;
    if (!s_side) {
        cudaStreamCreateWithFlags(&s_side, cudaStreamNonBlocking);
        cudaEventCreateWithFlags(&ev_fork, cudaEventDisableTiming);
        cudaEventCreateWithFlags(&ev_w1, cudaEventDisableTiming);
        cudaEventCreateWithFlags(&ev_join, cudaEventDisableTiming);
        cudaFuncSetAttribute(gemm1_hmma, cudaFuncAttributeMaxDynamicSharedMemorySize,
                             4 * SLAB0);
    }

    // fork side stream at capture start
    cudaEventRecord(ev_fork, 0);
    cudaStreamWaitEvent(s_side, ev_fork, 0);

    // side stream: W1 transpose, then CSR build
    transpose_w1<<<Nn / 32, 256, 0, s_side>>>(W1);
    cudaEventRecord(ev_w1, s_side);
    hist_kernel<<<(E / 8 + 255) / 256, 256, 0, s_side>>>(arow, E);
    scan_kernel<<<1, 1024, 0, s_side>>>();
    scatter_kernel<<<(E + 255) / 256, 256, 0, s_side>>>(arow, acol, aval, E);
    cudaEventRecord(ev_join, s_side);

    // main stream: setup, then GEMM1 (after W1T ready) + convert
    setup_kernel<<<512, 256>>>(blin, out);
    cudaStreamWaitEvent(0, ev_w1, 0);
    gemm1_hmma<<<4 * Nn / 64, 256, 4 * SLAB0>>>(x);
    convert_s1h<<<256, 256>>>();

    // join CSR, then spmm chain
    cudaStreamWaitEvent(0, ev_join, 0);
    spmm1_g2<<<(Nn * 32) / 256, 256>>>(b1, W2);
    spmm2_g3<<<(Nn * 32) / 256, 256>>>(b2, W3);
    final_fused<<<Nn / 8, 256>>>(b3, Wlin, out);
}

// round 15
// speedup vs baseline: 1.0990x; 1.0176x over previous
#include <cuda_runtime.h>
#include <cuda_fp16.h>
#include <cstdint>
#include <math.h>

#define Nn 8192
#define NH 64
#define NC 8
#define MAXE (Nn * 32)

// ------------------------- device scratch (static, no allocs) ----------------
__device__ float  g_S1[Nn * NH];
__device__ __half g_S1h[Nn * NH];
__device__ __half g_S2h[Nn * NH];
__device__ float  g_S3[Nn * NC];
__device__ __half g_W1T_hi[NH * Nn];
__device__ int   g_cnt[Nn];
__device__ int   g_off[Nn];
__device__ int   g_rowptr[Nn + 1];
__device__ int   g_cols[MAXE];
__device__ float g_vals[MAXE];

#define SWZ(o)  ((o) ^ (((o) >> 3) & 0x70))

// ------------------------- HMMA / async helpers ------------------------------
__device__ __forceinline__ void mma16816(float c[4], const uint32_t a[4],
                                         uint32_t b0, uint32_t b1) {
    asm volatile(
        "mma.sync.aligned.m16n8k16.row.col.f32.f16.f16.f32 "
        "{%0,%1,%2,%3}, {%4,%5,%6,%7}, {%8,%9}, {%0,%1,%2,%3};"
        : "+f"(c[0]), "+f"(c[1]), "+f"(c[2]), "+f"(c[3])
        : "r"(a[0]), "r"(a[1]), "r"(a[2]), "r"(a[3]), "r"(b0), "r"(b1));
}

__device__ __forceinline__ void ldsm_x4(uint32_t& r0, uint32_t& r1,
                                        uint32_t& r2, uint32_t& r3, uint32_t addr) {
    asm volatile("ldmatrix.sync.aligned.m8n8.x4.shared.b16 {%0,%1,%2,%3}, [%4];"
                 : "=r"(r0), "=r"(r1), "=r"(r2), "=r"(r3) : "r"(addr));
}

__device__ __forceinline__ void cp_async16(uint32_t dst, const void* src) {
    asm volatile("cp.async.cg.shared.global [%0], [%1], 16;" :: "r"(dst), "l"(src));
}
__device__ __forceinline__ void cp_commit() {
    asm volatile("cp.async.commit_group;");
}
template <int N>
__device__ __forceinline__ void cp_wait() {
    asm volatile("cp.async.wait_group %0;" :: "n"(N));
}

__device__ __forceinline__ uint32_t pack_h2(float x, float y) {
    __half2 h = __floats2half2_rn(x, y);
    return *reinterpret_cast<uint32_t*>(&h);
}

// ------------------------- setup: zero S1/cnt/off, out init ------------------
__global__ void setup_kernel(const float* __restrict__ blin, float* __restrict__ out) {
    int i = blockIdx.x * blockDim.x + threadIdx.x;
    reinterpret_cast<float4*>(g_S1)[i] = make_float4(0.f, 0.f, 0.f, 0.f);
    if (i < Nn) { g_cnt[i] = 0; g_off[i] = 0; }
    if (i < NC) out[i] = blin[0];
}

// ------------------------- hist (vectorized, 8/thread) -----------------------
__global__ void hist_kernel(const int* __restrict__ row, int E) {
    int i = (blockIdx.x * blockDim.x + threadIdx.x) * 8;
    if (i + 7 < E) {
        int4 r0 = *reinterpret_cast<const int4*>(row + i);
        int4 r1 = *reinterpret_cast<const int4*>(row + i + 4);
        atomicAdd(&g_cnt[r0.x], 1); atomicAdd(&g_cnt[r0.y], 1);
        atomicAdd(&g_cnt[r0.z], 1); atomicAdd(&g_cnt[r0.w], 1);
        atomicAdd(&g_cnt[r1.x], 1); atomicAdd(&g_cnt[r1.y], 1);
        atomicAdd(&g_cnt[r1.z], 1); atomicAdd(&g_cnt[r1.w], 1);
    } else {
        for (int j = i; j < E; j++) atomicAdd(&g_cnt[row[j]], 1);
    }
}

// ------------------------- W1 transpose (coalesced, smem tile) ---------------
__global__ void transpose_w1(const float* __restrict__ W1) {
    __shared__ float t[32][65];
    int k0 = blockIdx.x * 32;
    int tid = threadIdx.x;
    #pragma unroll
    for (int i = 0; i < 8; i++) {
        int j = tid + i * 256;
        int r = j >> 6, c = j & 63;
        t[r][c] = W1[(size_t)(k0 + r) * NH + c];
    }
    __syncthreads();
    #pragma unroll
    for (int i = 0; i < 8; i++) {
        int j = tid + i * 256;
        int c = j >> 5, r = j & 31;
        g_W1T_hi[(size_t)c * Nn + k0 + r] = __float2half_rn(t[r][c]);
    }
}

// ------------------------- shfl exclusive scan (1024 threads) ----------------
__global__ void scan_kernel() {
    __shared__ int wsum[32];
    int t = threadIdx.x, lane = t & 31, w = t >> 5;
    int base = t * 8;
    int s = 0;
    #pragma unroll
    for (int i = 0; i < 8; i++) s += g_cnt[base + i];
    int incl = s;
    #pragma unroll
    for (int o = 1; o < 32; o <<= 1) {
        int v = __shfl_up_sync(0xFFFFFFFFu, incl, o);
        if (lane >= o) incl += v;
    }
    if (lane == 31) wsum[w] = incl;
    __syncthreads();
    if (w == 0) {
        int v = wsum[lane];
        int iw = v;
        #pragma unroll
        for (int o = 1; o < 32; o <<= 1) {
            int u = __shfl_up_sync(0xFFFFFFFFu, iw, o);
            if (lane >= o) iw += u;
        }
        wsum[lane] = iw - v;
    }
    __syncthreads();
    int acc = incl - s + wsum[w];
    #pragma unroll
    for (int i = 0; i < 8; i++) { g_rowptr[base + i] = acc; acc += g_cnt[base + i]; }
    if (t == 1023) g_rowptr[Nn] = acc;
}

__global__ void scatter_kernel(const int* __restrict__ row, const int* __restrict__ col,
                               const float* __restrict__ val, int E) {
    int e = blockIdx.x * blockDim.x + threadIdx.x;
    if (e < E) {
        int r = row[e];
        int p = g_rowptr[r] + atomicAdd(&g_off[r], 1);
        g_cols[p] = col[e];
        g_vals[p] = val[e];
    }
}

// ------------------------- HMMA GEMM1 (R11 proven config) --------------------
// S1 += x @ W1. K split x4 (grid 512, 2 CTAs/SM). 4 stages x 25.6KB,
// prefetch 3, wait_group 2, commit every iteration. A via cp.async fp32
// swizzled smem -> cvt at fragment read; B (144B padded rows) via ldmatrix.x4.
#define SLAB0 25600
__global__ void __launch_bounds__(256, 2)
gemm1_hmma(const float* __restrict__ Aext) {
    extern __shared__ char smem[];
    const uint32_t sb = (uint32_t)__cvta_generic_to_shared(smem);
    const int tid = threadIdx.x, lane = tid & 31, w = tid >> 5;
    const int wm = (w & 3) * 16, wn = (w >> 2) * 32;
    const int g = lane >> 2, tg = lane & 3;

    float acc[4][4];
    #pragma unroll
    for (int nt = 0; nt < 4; nt++)
        #pragma unroll
        for (int q = 0; q < 4; q++) acc[nt][q] = 0.f;

    uint32_t aoff[16];
    #pragma unroll
    for (int ks = 0; ks < 4; ks++)
        #pragma unroll
        for (int i = 0; i < 4; i++) {
            uint32_t o = (uint32_t)((wm + g + (i & 1) * 8) * 256 +
                                    ks * 64 + tg * 8 + (i >> 1) * 32);
            aoff[ks * 4 + i] = SWZ(o);
        }

    const int m0 = (blockIdx.x >> 2) * 64;
    const int kq = blockIdx.x & 3;
    const float* abase = Aext + (size_t)(m0 + (tid >> 4)) * Nn + kq * 2048 + (tid & 15) * 4;
    const uint32_t adst0 = SWZ((uint32_t)((tid >> 4) * 256 + (tid & 15) * 16));
    const __half* bbase = g_W1T_hi + (size_t)(tid >> 3) * Nn + kq * 2048 + (tid & 7) * 8;
    const uint32_t bdst0 = 16384u + (tid >> 3) * 144 + (tid & 7) * 16;
    const uint32_t lmb = 16384u +
        (uint32_t)((wn + ((lane >> 4) * 8) + (lane & 7)) * 144 + ((lane >> 3) & 1) * 16);

    auto issue = [&](int kc) {
        uint32_t dbase = sb + (kc & 3) * SLAB0;
        const float* as = abase + kc * 64;
        #pragma unroll
        for (int ii = 0; ii < 4; ii++)
            cp_async16(dbase + adst0 + ii * 4096, as + ii * 16 * Nn);
        const __half* bs = bbase + kc * 64;
        #pragma unroll
        for (int ii = 0; ii < 2; ii++)
            cp_async16(dbase + bdst0 + ii * 32 * 144, bs + ii * 32 * Nn);
    };

    issue(0); cp_commit();
    issue(1); cp_commit();
    issue(2); cp_commit();
    #pragma unroll 1
    for (int kc = 0; kc < 32; kc++) {
        cp_wait<2>();
        __syncthreads();
        if (kc + 3 < 32) issue(kc + 3);
        cp_commit();
        const char* base = smem + (kc & 3) * SLAB0;
        const uint32_t bb = sb + (kc & 3) * SLAB0 + lmb;
        #pragma unroll
        for (int ks = 0; ks < 4; ks++) {
            uint32_t ah[4];
            #pragma unroll
            for (int i = 0; i < 4; i++) {
                float2 v = *reinterpret_cast<const float2*>(base + aoff[ks * 4 + i]);
                ah[i] = pack_h2(v.x, v.y);
            }
            uint32_t b00, b01, b10, b11, b20, b21, b30, b31;
            ldsm_x4(b00, b01, b10, b11, bb + ks * 32);
            ldsm_x4(b20, b21, b30, b31, bb + ks * 32 + 2304);
            mma16816(acc[0], ah, b00, b01);
            mma16816(acc[1], ah, b10, b11);
            mma16816(acc[2], ah, b20, b21);
            mma16816(acc[3], ah, b30, b31);
        }
    }
    #pragma unroll
    for (int nt = 0; nt < 4; nt++) {
        int row = m0 + wm + g;
        int col = wn + nt * 8 + 2 * tg;
        atomicAdd(&g_S1[(size_t)row * 64 + col],           acc[nt][0]);
        atomicAdd(&g_S1[(size_t)row * 64 + col + 1],       acc[nt][1]);
        atomicAdd(&g_S1[(size_t)(row + 8) * 64 + col],     acc[nt][2]);
        atomicAdd(&g_S1[(size_t)(row + 8) * 64 + col + 1], acc[nt][3]);
    }
}

// ------------------------- S1 fp32 -> fp16 convert ---------------------------
__global__ void convert_s1h() {
    int i = blockIdx.x * blockDim.x + threadIdx.x;
    const float4* src = reinterpret_cast<const float4*>(g_S1);
    float4 a = src[2 * i], b = src[2 * i + 1];
    uint4 u;
    u.x = pack_h2(a.x, a.y);
    u.y = pack_h2(a.z, a.w);
    u.z = pack_h2(b.x, b.y);
    u.w = pack_h2(b.z, b.w);
    reinterpret_cast<uint4*>(g_S1h)[i] = u;
}

// ------------------------- SpMM1 (fp16 gathers, unroll 8) + GEMM2 ------------
__global__ void spmm1_g2(const float* __restrict__ b1, const float* __restrict__ W2) {
    __shared__ float w2s[NH * NH];
    int tid = threadIdx.x;
    #pragma unroll
    for (int i = 0; i < 16; i++) w2s[tid + i * 256] = W2[tid + i * 256];
    __syncthreads();
    int gt = blockIdx.x * blockDim.x + tid;
    int row = gt >> 5, lane = gt & 31;
    int s = g_rowptr[row], e = g_rowptr[row + 1];
    const __half2* S = reinterpret_cast<const __half2*>(g_S1h);
    float a0 = 0.f, a1 = 0.f;
    int i = s;
    for (; i + 8 <= e; i += 8) {
        float2 f[8];
        #pragma unroll
        for (int j = 0; j < 8; j++)
            f[j] = __half22float2(S[(size_t)g_cols[i + j] * 32 + lane]);
        #pragma unroll
        for (int j = 0; j < 8; j++) {
            float v = g_vals[i + j];
            a0 += v * f[j].x; a1 += v * f[j].y;
        }
    }
    for (; i < e; i++) {
        float2 f = __half22float2(S[(size_t)g_cols[i] * 32 + lane]);
        float v = g_vals[i];
        a0 += v * f.x; a1 += v * f.y;
    }
    float2 bb = *reinterpret_cast<const float2*>(b1 + 2 * lane);
    float r0 = fmaxf(a0 + bb.x, 0.f);
    float r1 = fmaxf(a1 + bb.y, 0.f);
    float acc0 = 0.f, acc1 = 0.f;
    #pragma unroll
    for (int j = 0; j < 32; j++) {
        float hk0 = __shfl_sync(0xFFFFFFFFu, r0, j);
        float hk1 = __shfl_sync(0xFFFFFFFFu, r1, j);
        float2 wa = *reinterpret_cast<const float2*>(w2s + (2 * j) * 64 + 2 * lane);
        float2 wb = *reinterpret_cast<const float2*>(w2s + (2 * j + 1) * 64 + 2 * lane);
        acc0 += hk0 * wa.x + hk1 * wb.x;
        acc1 += hk0 * wa.y + hk1 * wb.y;
    }
    reinterpret_cast<__half2*>(g_S2h)[(size_t)row * 32 + lane] =
        __floats2half2_rn(acc0, acc1);
}

// ------------------------- SpMM2 (fp16 gathers, unroll 8) + gemm3 ------------
__global__ void spmm2_g3(const float* __restrict__ b2, const float* __restrict__ W3) {
    __shared__ float w3t[NC * NH];
    int tid = threadIdx.x;
    #pragma unroll
    for (int ii = 0; ii < 2; ii++) {
        int i = tid + ii * 256;
        w3t[(i & 7) * 64 + (i >> 3)] = W3[i];
    }
    __syncthreads();
    int gt = blockIdx.x * blockDim.x + tid;
    int row = gt >> 5, lane = gt & 31;
    int s = g_rowptr[row], e = g_rowptr[row + 1];
    const __half2* S = reinterpret_cast<const __half2*>(g_S2h);
    float a0 = 0.f, a1 = 0.f;
    int i = s;
    for (; i + 8 <= e; i += 8) {
        float2 f[8];
        #pragma unroll
        for (int j = 0; j < 8; j++)
            f[j] = __half22float2(S[(size_t)g_cols[i + j] * 32 + lane]);
        #pragma unroll
        for (int j = 0; j < 8; j++) {
            float v = g_vals[i + j];
            a0 += v * f[j].x; a1 += v * f[j].y;
        }
    }
    for (; i < e; i++) {
        float2 f = __half22float2(S[(size_t)g_cols[i] * 32 + lane]);
        float v = g_vals[i];
        a0 += v * f.x; a1 += v * f.y;
    }
    float2 bb = *reinterpret_cast<const float2*>(b2 + 2 * lane);
    float r0 = fmaxf(a0 + bb.x, 0.f);
    float r1 = fmaxf(a1 + bb.y, 0.f);
    float p[NC];
    #pragma unroll
    for (int f = 0; f < NC; f++) {
        float2 wv = *reinterpret_cast<const float2*>(w3t + f * 64 + 2 * lane);
        p[f] = r0 * wv.x + r1 * wv.y;
    }
    #pragma unroll
    for (int o = 16; o > 0; o >>= 1)
        #pragma unroll
        for (int f = 0; f < NC; f++) p[f] += __shfl_xor_sync(0xFFFFFFFFu, p[f], o);
    if (lane == 0) {
        float* o8 = g_S3 + (size_t)row * NC;
        *reinterpret_cast<float4*>(o8)     = make_float4(p[0], p[1], p[2], p[3]);
        *reinterpret_cast<float4*>(o8 + 4) = make_float4(p[4], p[5], p[6], p[7]);
    }
}

// ------------------------- final: warp-per-row spmm8 + softmax + head --------
__global__ void final_fused(const float* __restrict__ b3, const float* __restrict__ Wlin,
                            float* __restrict__ out) {
    __shared__ float red[8][NC];
    int t = threadIdx.x, lane = t & 31, wp = t >> 5;
    int row = blockIdx.x * 8 + wp;
    float acc[NC];
    #pragma unroll
    for (int f = 0; f < NC; f++) acc[f] = 0.f;
    int s = g_rowptr[row], e = g_rowptr[row + 1];
    for (int i = s + lane; i < e; i += 32) {
        int c = g_cols[i];
        float v = g_vals[i];
        const float4* p = reinterpret_cast<const float4*>(g_S3 + (size_t)c * NC);
        float4 q0 = p[0], q1 = p[1];
        acc[0] += v * q0.x; acc[1] += v * q0.y; acc[2] += v * q0.z; acc[3] += v * q0.w;
        acc[4] += v * q1.x; acc[5] += v * q1.y; acc[6] += v * q1.z; acc[7] += v * q1.w;
    }
    #pragma unroll
    for (int o = 16; o > 0; o >>= 1)
        #pragma unroll
        for (int f = 0; f < NC; f++) acc[f] += __shfl_xor_sync(0xFFFFFFFFu, acc[f], o);
    if (lane == 0) {
        float h[NC];
        #pragma unroll
        for (int f = 0; f < NC; f++) h[f] = acc[f] + b3[f];
        float m = h[0];
        #pragma unroll
        for (int f = 1; f < NC; f++) m = fmaxf(m, h[f]);
        float ssum = 0.f;
        #pragma unroll
        for (int f = 0; f < NC; f++) ssum += expf(h[f] - m);
        float lse = m + logf(ssum);
        float wv = Wlin[row];
        #pragma unroll
        for (int f = 0; f < NC; f++) red[wp][f] = (h[f] - lse) * wv;
    }
    __syncthreads();
    if (t < NC) {
        float ssum = 0.f;
        #pragma unroll
        for (int j = 0; j < 8; j++) ssum += red[j][t];
        atomicAdd(&out[t], ssum);
    }
}

// ------------------------- launch (R11 structure) -----------------------------
extern "C" void kernel_launch(void* const* d_in, const int* in_sizes, int n_in,
                              void* d_out, int out_size) {
    const float* x    = (const float*)d_in[0];
    const int*   arow = (const int*)d_in[1];
    const int*   acol = (const int*)d_in[2];
    const float* aval = (const float*)d_in[3];
    const float* W1   = (const float*)d_in[4];
    const float* b1   = (const float*)d_in[5];
    const float* W2   = (const float*)d_in[6];
    const float* b2   = (const float*)d_in[7];
    const float* W3   = (const float*)d_in[8];
    const float* b3   = (const float*)d_in[9];
    const float* Wlin = (const float*)d_in[10];
    const float* blin = (const float*)d_in[11];
    const int E = in_sizes[1];
    float* out = (float*)d_out;

    static cudaStream_t s_side = nullptr;
    static cudaEvent_t ev_fork, ev_join;
    if (!s_side) {
        cudaStreamCreateWithFlags(&s_side, cudaStreamNonBlocking);
        cudaEventCreateWithFlags(&ev_fork, cudaEventDisableTiming);
        cudaEventCreateWithFlags(&ev_join, cudaEventDisableTiming);
        cudaFuncSetAttribute(gemm1_hmma, cudaFuncAttributeMaxDynamicSharedMemorySize,
                             4 * SLAB0);
    }

    // main stream: setup (zero S1 + cnt/off, out init)
    setup_kernel<<<512, 256>>>(blin, out);
    cudaEventRecord(ev_fork, 0);

    // side stream: CSR build (overlaps GEMM1 chain)
    cudaStreamWaitEvent(s_side, ev_fork, 0);
    hist_kernel<<<(E / 8 + 255) / 256, 256, 0, s_side>>>(arow, E);
    scan_kernel<<<1, 1024, 0, s_side>>>();
    scatter_kernel<<<(E + 255) / 256, 256, 0, s_side>>>(arow, acol, aval, E);
    cudaEventRecord(ev_join, s_side);

    // main stream: W1 prep + GEMM1 + fp16 convert
    transpose_w1<<<Nn / 32, 256>>>(W1);
    gemm1_hmma<<<4 * Nn / 64, 256, 4 * SLAB0>>>(x);
    convert_s1h<<<256, 256>>>();

    // join, then the spmm chain
    cudaStreamWaitEvent(0, ev_join, 0);
    spmm1_g2<<<(Nn * 32) / 256, 256>>>(b1, W2);
    spmm2_g3<<<(Nn * 32) / 256, 256>>>(b2, W3);
    final_fused<<<Nn / 8, 256>>>(b3, Wlin, out);
}

// round 16
// speedup vs baseline: 1.1428x; 1.0398x over previous
#include <cuda_runtime.h>
#include <cuda_fp16.h>
#include <cstdint>
#include <math.h>

#define Nn 8192
#define NH 64
#define NC 8
#define MAXE (Nn * 32)

// ------------------------- device scratch (static, no allocs) ----------------
__device__ __half g_S1h[Nn * NH];
__device__ __half g_S2h[Nn * NH];
__device__ float  g_S3[Nn * NC];
__device__ __half g_W1T_hi[NH * Nn];
__device__ int   g_cnt[Nn];
__device__ int   g_off[Nn];
__device__ int   g_rowptr[Nn + 1];
__device__ int   g_cols[MAXE];
__device__ float g_vals[MAXE];

#define SWZ(o)  ((o) ^ (((o) >> 3) & 0x70))

// ------------------------- HMMA / async helpers ------------------------------
__device__ __forceinline__ void mma16816(float c[4], const uint32_t a[4],
                                         uint32_t b0, uint32_t b1) {
    asm volatile(
        "mma.sync.aligned.m16n8k16.row.col.f32.f16.f16.f32 "
        "{%0,%1,%2,%3}, {%4,%5,%6,%7}, {%8,%9}, {%0,%1,%2,%3};"
        : "+f"(c[0]), "+f"(c[1]), "+f"(c[2]), "+f"(c[3])
        : "r"(a[0]), "r"(a[1]), "r"(a[2]), "r"(a[3]), "r"(b0), "r"(b1));
}

__device__ __forceinline__ void ldsm_x4(uint32_t& r0, uint32_t& r1,
                                        uint32_t& r2, uint32_t& r3, uint32_t addr) {
    asm volatile("ldmatrix.sync.aligned.m8n8.x4.shared.b16 {%0,%1,%2,%3}, [%4];"
                 : "=r"(r0), "=r"(r1), "=r"(r2), "=r"(r3) : "r"(addr));
}

__device__ __forceinline__ void cp_async16(uint32_t dst, const void* src) {
    asm volatile("cp.async.cg.shared.global [%0], [%1], 16;" :: "r"(dst), "l"(src));
}
__device__ __forceinline__ void cp_commit() {
    asm volatile("cp.async.commit_group;");
}
template <int N>
__device__ __forceinline__ void cp_wait() {
    asm volatile("cp.async.wait_group %0;" :: "n"(N));
}

__device__ __forceinline__ uint32_t pack_h2(float x, float y) {
    __half2 h = __floats2half2_rn(x, y);
    return *reinterpret_cast<uint32_t*>(&h);
}

// ------------------------- setup: zero S1h/cnt/off, out init -----------------
__global__ void setup_kernel(const float* __restrict__ blin, float* __restrict__ out) {
    int i = blockIdx.x * blockDim.x + threadIdx.x;   // grid 512x256 = 131072
    if (i < 65536)
        reinterpret_cast<uint4*>(g_S1h)[i] = make_uint4(0, 0, 0, 0);
    if (i < Nn) { g_cnt[i] = 0; g_off[i] = 0; }
    if (i < NC) out[i] = blin[0];
}

// ------------------------- hist (vectorized, 8/thread) -----------------------
__global__ void hist_kernel(const int* __restrict__ row, int E) {
    int i = (blockIdx.x * blockDim.x + threadIdx.x) * 8;
    if (i + 7 < E) {
        int4 r0 = *reinterpret_cast<const int4*>(row + i);
        int4 r1 = *reinterpret_cast<const int4*>(row + i + 4);
        atomicAdd(&g_cnt[r0.x], 1); atomicAdd(&g_cnt[r0.y], 1);
        atomicAdd(&g_cnt[r0.z], 1); atomicAdd(&g_cnt[r0.w], 1);
        atomicAdd(&g_cnt[r1.x], 1); atomicAdd(&g_cnt[r1.y], 1);
        atomicAdd(&g_cnt[r1.z], 1); atomicAdd(&g_cnt[r1.w], 1);
    } else {
        for (int j = i; j < E; j++) atomicAdd(&g_cnt[row[j]], 1);
    }
}

// ------------------------- W1 transpose (coalesced, smem tile) ---------------
__global__ void transpose_w1(const float* __restrict__ W1) {
    __shared__ float t[32][65];
    int k0 = blockIdx.x * 32;
    int tid = threadIdx.x;
    #pragma unroll
    for (int i = 0; i < 8; i++) {
        int j = tid + i * 256;
        int r = j >> 6, c = j & 63;
        t[r][c] = W1[(size_t)(k0 + r) * NH + c];
    }
    __syncthreads();
    #pragma unroll
    for (int i = 0; i < 8; i++) {
        int j = tid + i * 256;
        int c = j >> 5, r = j & 31;
        g_W1T_hi[(size_t)c * Nn + k0 + r] = __float2half_rn(t[r][c]);
    }
}

// ------------------------- shfl exclusive scan (1024 threads) ----------------
__global__ void scan_kernel() {
    __shared__ int wsum[32];
    int t = threadIdx.x, lane = t & 31, w = t >> 5;
    int base = t * 8;
    int s = 0;
    #pragma unroll
    for (int i = 0; i < 8; i++) s += g_cnt[base + i];
    int incl = s;
    #pragma unroll
    for (int o = 1; o < 32; o <<= 1) {
        int v = __shfl_up_sync(0xFFFFFFFFu, incl, o);
        if (lane >= o) incl += v;
    }
    if (lane == 31) wsum[w] = incl;
    __syncthreads();
    if (w == 0) {
        int v = wsum[lane];
        int iw = v;
        #pragma unroll
        for (int o = 1; o < 32; o <<= 1) {
            int u = __shfl_up_sync(0xFFFFFFFFu, iw, o);
            if (lane >= o) iw += u;
        }
        wsum[lane] = iw - v;
    }
    __syncthreads();
    int acc = incl - s + wsum[w];
    #pragma unroll
    for (int i = 0; i < 8; i++) { g_rowptr[base + i] = acc; acc += g_cnt[base + i]; }
    if (t == 1023) g_rowptr[Nn] = acc;
}

__global__ void scatter_kernel(const int* __restrict__ row, const int* __restrict__ col,
                               const float* __restrict__ val, int E) {
    int e = blockIdx.x * blockDim.x + threadIdx.x;
    if (e < E) {
        int r = row[e];
        int p = g_rowptr[r] + atomicAdd(&g_off[r], 1);
        g_cols[p] = col[e];
        g_vals[p] = val[e];
    }
}

// ------------------------- HMMA GEMM1 (R11 pipeline, fp16 atomic epilogue) ---
// S1h += x @ W1 (half2 atomicAdd into zeroed g_S1h; 4 addends/elem).
// K split x4 (grid 512, 2 CTAs/SM). 4 stages x 25.6KB, prefetch 3,
// wait_group 2, commit every iteration. A via cp.async fp32 swizzled smem;
// B (144B padded rows) via ldmatrix.x4.
#define SLAB0 25600
__global__ void __launch_bounds__(256, 2)
gemm1_hmma(const float* __restrict__ Aext) {
    extern __shared__ char smem[];
    const uint32_t sb = (uint32_t)__cvta_generic_to_shared(smem);
    const int tid = threadIdx.x, lane = tid & 31, w = tid >> 5;
    const int wm = (w & 3) * 16, wn = (w >> 2) * 32;
    const int g = lane >> 2, tg = lane & 3;

    float acc[4][4];
    #pragma unroll
    for (int nt = 0; nt < 4; nt++)
        #pragma unroll
        for (int q = 0; q < 4; q++) acc[nt][q] = 0.f;

    uint32_t aoff[16];
    #pragma unroll
    for (int ks = 0; ks < 4; ks++)
        #pragma unroll
        for (int i = 0; i < 4; i++) {
            uint32_t o = (uint32_t)((wm + g + (i & 1) * 8) * 256 +
                                    ks * 64 + tg * 8 + (i >> 1) * 32);
            aoff[ks * 4 + i] = SWZ(o);
        }

    const int m0 = (blockIdx.x >> 2) * 64;
    const int kq = blockIdx.x & 3;
    const float* abase = Aext + (size_t)(m0 + (tid >> 4)) * Nn + kq * 2048 + (tid & 15) * 4;
    const uint32_t adst0 = SWZ((uint32_t)((tid >> 4) * 256 + (tid & 15) * 16));
    const __half* bbase = g_W1T_hi + (size_t)(tid >> 3) * Nn + kq * 2048 + (tid & 7) * 8;
    const uint32_t bdst0 = 16384u + (tid >> 3) * 144 + (tid & 7) * 16;
    const uint32_t lmb = 16384u +
        (uint32_t)((wn + ((lane >> 4) * 8) + (lane & 7)) * 144 + ((lane >> 3) & 1) * 16);

    auto issue = [&](int kc) {
        uint32_t dbase = sb + (kc & 3) * SLAB0;
        const float* as = abase + kc * 64;
        #pragma unroll
        for (int ii = 0; ii < 4; ii++)
            cp_async16(dbase + adst0 + ii * 4096, as + ii * 16 * Nn);
        const __half* bs = bbase + kc * 64;
        #pragma unroll
        for (int ii = 0; ii < 2; ii++)
            cp_async16(dbase + bdst0 + ii * 32 * 144, bs + ii * 32 * Nn);
    };

    issue(0); cp_commit();
    issue(1); cp_commit();
    issue(2); cp_commit();
    #pragma unroll 1
    for (int kc = 0; kc < 32; kc++) {
        cp_wait<2>();
        __syncthreads();
        if (kc + 3 < 32) issue(kc + 3);
        cp_commit();
        const char* base = smem + (kc & 3) * SLAB0;
        const uint32_t bb = sb + (kc & 3) * SLAB0 + lmb;
        #pragma unroll
        for (int ks = 0; ks < 4; ks++) {
            uint32_t ah[4];
            #pragma unroll
            for (int i = 0; i < 4; i++) {
                float2 v = *reinterpret_cast<const float2*>(base + aoff[ks * 4 + i]);
                ah[i] = pack_h2(v.x, v.y);
            }
            uint32_t b00, b01, b10, b11, b20, b21, b30, b31;
            ldsm_x4(b00, b01, b10, b11, bb + ks * 32);
            ldsm_x4(b20, b21, b30, b31, bb + ks * 32 + 2304);
            mma16816(acc[0], ah, b00, b01);
            mma16816(acc[1], ah, b10, b11);
            mma16816(acc[2], ah, b20, b21);
            mma16816(acc[3], ah, b30, b31);
        }
    }
    #pragma unroll
    for (int nt = 0; nt < 4; nt++) {
        int row = m0 + wm + g;
        int col = wn + nt * 8 + 2 * tg;
        atomicAdd(reinterpret_cast<__half2*>(g_S1h + (size_t)row * 64 + col),
                  __floats2half2_rn(acc[nt][0], acc[nt][1]));
        atomicAdd(reinterpret_cast<__half2*>(g_S1h + (size_t)(row + 8) * 64 + col),
                  __floats2half2_rn(acc[nt][2], acc[nt][3]));
    }
}

// ------------------------- SpMM1 (fp16 gathers, unroll 8) + GEMM2 ------------
__global__ void spmm1_g2(const float* __restrict__ b1, const float* __restrict__ W2) {
    __shared__ float w2s[NH * NH];
    int tid = threadIdx.x;
    #pragma unroll
    for (int i = 0; i < 16; i++) w2s[tid + i * 256] = W2[tid + i * 256];
    __syncthreads();
    int gt = blockIdx.x * blockDim.x + tid;
    int row = gt >> 5, lane = gt & 31;
    int s = g_rowptr[row], e = g_rowptr[row + 1];
    const __half2* S = reinterpret_cast<const __half2*>(g_S1h);
    float a0 = 0.f, a1 = 0.f;
    int i = s;
    for (; i + 8 <= e; i += 8) {
        float2 f[8];
        #pragma unroll
        for (int j = 0; j < 8; j++)
            f[j] = __half22float2(S[(size_t)g_cols[i + j] * 32 + lane]);
        #pragma unroll
        for (int j = 0; j < 8; j++) {
            float v = g_vals[i + j];
            a0 += v * f[j].x; a1 += v * f[j].y;
        }
    }
    for (; i < e; i++) {
        float2 f = __half22float2(S[(size_t)g_cols[i] * 32 + lane]);
        float v = g_vals[i];
        a0 += v * f.x; a1 += v * f.y;
    }
    float2 bb = *reinterpret_cast<const float2*>(b1 + 2 * lane);
    float r0 = fmaxf(a0 + bb.x, 0.f);
    float r1 = fmaxf(a1 + bb.y, 0.f);
    float acc0 = 0.f, acc1 = 0.f;
    #pragma unroll
    for (int j = 0; j < 32; j++) {
        float hk0 = __shfl_sync(0xFFFFFFFFu, r0, j);
        float hk1 = __shfl_sync(0xFFFFFFFFu, r1, j);
        float2 wa = *reinterpret_cast<const float2*>(w2s + (2 * j) * 64 + 2 * lane);
        float2 wb = *reinterpret_cast<const float2*>(w2s + (2 * j + 1) * 64 + 2 * lane);
        acc0 += hk0 * wa.x + hk1 * wb.x;
        acc1 += hk0 * wa.y + hk1 * wb.y;
    }
    reinterpret_cast<__half2*>(g_S2h)[(size_t)row * 32 + lane] =
        __floats2half2_rn(acc0, acc1);
}

// ------------------------- SpMM2 (fp16 gathers, unroll 8) + gemm3 ------------
__global__ void spmm2_g3(const float* __restrict__ b2, const float* __restrict__ W3) {
    __shared__ float w3t[NC * NH];
    int tid = threadIdx.x;
    #pragma unroll
    for (int ii = 0; ii < 2; ii++) {
        int i = tid + ii * 256;
        w3t[(i & 7) * 64 + (i >> 3)] = W3[i];
    }
    __syncthreads();
    int gt = blockIdx.x * blockDim.x + tid;
    int row = gt >> 5, lane = gt & 31;
    int s = g_rowptr[row], e = g_rowptr[row + 1];
    const __half2* S = reinterpret_cast<const __half2*>(g_S2h);
    float a0 = 0.f, a1 = 0.f;
    int i = s;
    for (; i + 8 <= e; i += 8) {
        float2 f[8];
        #pragma unroll
        for (int j = 0; j < 8; j++)
            f[j] = __half22float2(S[(size_t)g_cols[i + j] * 32 + lane]);
        #pragma unroll
        for (int j = 0; j < 8; j++) {
            float v = g_vals[i + j];
            a0 += v * f[j].x; a1 += v * f[j].y;
        }
    }
    for (; i < e; i++) {
        float2 f = __half22float2(S[(size_t)g_cols[i] * 32 + lane]);
        float v = g_vals[i];
        a0 += v * f.x; a1 += v * f.y;
    }
    float2 bb = *reinterpret_cast<const float2*>(b2 + 2 * lane);
    float r0 = fmaxf(a0 + bb.x, 0.f);
    float r1 = fmaxf(a1 + bb.y, 0.f);
    float p[NC];
    #pragma unroll
    for (int f = 0; f < NC; f++) {
        float2 wv = *reinterpret_cast<const float2*>(w3t + f * 64 + 2 * lane);
        p[f] = r0 * wv.x + r1 * wv.y;
    }
    #pragma unroll
    for (int o = 16; o > 0; o >>= 1)
        #pragma unroll
        for (int f = 0; f < NC; f++) p[f] += __shfl_xor_sync(0xFFFFFFFFu, p[f], o);
    if (lane == 0) {
        float* o8 = g_S3 + (size_t)row * NC;
        *reinterpret_cast<float4*>(o8)     = make_float4(p[0], p[1], p[2], p[3]);
        *reinterpret_cast<float4*>(o8 + 4) = make_float4(p[4], p[5], p[6], p[7]);
    }
}

// ------------------------- final: warp-per-row spmm8 + softmax + head --------
__global__ void final_fused(const float* __restrict__ b3, const float* __restrict__ Wlin,
                            float* __restrict__ out) {
    __shared__ float red[8][NC];
    int t = threadIdx.x, lane = t & 31, wp = t >> 5;
    int row = blockIdx.x * 8 + wp;
    float acc[NC];
    #pragma unroll
    for (int f = 0; f < NC; f++) acc[f] = 0.f;
    int s = g_rowptr[row], e = g_rowptr[row + 1];
    for (int i = s + lane; i < e; i += 32) {
        int c = g_cols[i];
        float v = g_vals[i];
        const float4* p = reinterpret_cast<const float4*>(g_S3 + (size_t)c * NC);
        float4 q0 = p[0], q1 = p[1];
        acc[0] += v * q0.x; acc[1] += v * q0.y; acc[2] += v * q0.z; acc[3] += v * q0.w;
        acc[4] += v * q1.x; acc[5] += v * q1.y; acc[6] += v * q1.z; acc[7] += v * q1.w;
    }
    #pragma unroll
    for (int o = 16; o > 0; o >>= 1)
        #pragma unroll
        for (int f = 0; f < NC; f++) acc[f] += __shfl_xor_sync(0xFFFFFFFFu, acc[f], o);
    if (lane == 0) {
        float h[NC];
        #pragma unroll
        for (int f = 0; f < NC; f++) h[f] = acc[f] + b3[f];
        float m = h[0];
        #pragma unroll
        for (int f = 1; f < NC; f++) m = fmaxf(m, h[f]);
        float ssum = 0.f;
        #pragma unroll
        for (int f = 0; f < NC; f++) ssum += expf(h[f] - m);
        float lse = m + logf(ssum);
        float wv = Wlin[row];
        #pragma unroll
        for (int f = 0; f < NC; f++) red[wp][f] = (h[f] - lse) * wv;
    }
    __syncthreads();
    if (t < NC) {
        float ssum = 0.f;
        #pragma unroll
        for (int j = 0; j < 8; j++) ssum += red[j][t];
        atomicAdd(&out[t], ssum);
    }
}

// ------------------------- launch (R11 structure, no convert) -----------------
extern "C" void kernel_launch(void* const* d_in, const int* in_sizes, int n_in,
                              void* d_out, int out_size) {
    const float* x    = (const float*)d_in[0];
    const int*   arow = (const int*)d_in[1];
    const int*   acol = (const int*)d_in[2];
    const float* aval = (const float*)d_in[3];
    const float* W1   = (const float*)d_in[4];
    const float* b1   = (const float*)d_in[5];
    const float* W2   = (const float*)d_in[6];
    const float* b2   = (const float*)d_in[7];
    const float* W3   = (const float*)d_in[8];
    const float* b3   = (const float*)d_in[9];
    const float* Wlin = (const float*)d_in[10];
    const float* blin = (const float*)d_in[11];
    const int E = in_sizes[1];
    float* out = (float*)d_out;

    static cudaStream_t s_side = nullptr;
    static cudaEvent_t ev_fork, ev_join;
    if (!s_side) {
        cudaStreamCreateWithFlags(&s_side, cudaStreamNonBlocking);
        cudaEventCreateWithFlags(&ev_fork, cudaEventDisableTiming);
        cudaEventCreateWithFlags(&ev_join, cudaEventDisableTiming);
        cudaFuncSetAttribute(gemm1_hmma, cudaFuncAttributeMaxDynamicSharedMemorySize,
                             4 * SLAB0);
    }

    // main stream: setup (zero S1h + cnt/off, out init)
    setup_kernel<<<512, 256>>>(blin, out);
    cudaEventRecord(ev_fork, 0);

    // side stream: CSR build (overlaps GEMM1 chain)
    cudaStreamWaitEvent(s_side, ev_fork, 0);
    hist_kernel<<<(E / 8 + 255) / 256, 256, 0, s_side>>>(arow, E);
    scan_kernel<<<1, 1024, 0, s_side>>>();
    scatter_kernel<<<(E + 255) / 256, 256, 0, s_side>>>(arow, acol, aval, E);
    cudaEventRecord(ev_join, s_side);

    // main stream: W1 prep + GEMM1 (fp16 atomic epilogue; no convert needed)
    transpose_w1<<<Nn / 32, 256>>>(W1);
    gemm1_hmma<<<4 * Nn / 64, 256, 4 * SLAB0>>>(x);

    // join, then the spmm chain
    cudaStreamWaitEvent(0, ev_join, 0);
    spmm1_g2<<<(Nn * 32) / 256, 256>>>(b1, W2);
    spmm2_g3<<<(Nn * 32) / 256, 256>>>(b2, W3);
    final_fused<<<Nn / 8, 256>>>(b3, Wlin, out);
}